// round 3
// baseline (speedup 1.0000x reference)
#include <cuda_runtime.h>
#include <cuda_bf16.h>
#include <cstdint>

#define N_NODES 100000
#define N_EDGES 1600000
#define D 128            // D_IN == D_OUT == 128
#define KTOT 256
#define EPS 1e-5f

// ---------------- scratch (no allocation allowed) ----------------
__device__ float g_aggr[(size_t)N_NODES * D];   // segment_sum result
__device__ float g_h[(size_t)N_NODES * D];      // pre-BN activations
__device__ float g_sum[D];
__device__ float g_sumsq[D];
__device__ float g_scale[D];
__device__ float g_shift[D];
__device__ int   g_idx_is64;                    // 1 if edge_index is int64

// ---------------- kernel 0: detect edge_index dtype ----------------
// For int64 data with values in [0, 2^31), every odd int32 word (high half)
// is zero. For int32 data, odd words are random node ids (~1e-5 chance of 0
// each). 64 samples make misdetection impossible in practice.
__global__ void probe_kernel(const int* __restrict__ e) {
    __shared__ int nz;
    if (threadIdx.x == 0) nz = 0;
    __syncthreads();
    // sample odd positions across the buffer
    int v = e[threadIdx.x * 2 + 1];
    if (v != 0) atomicAdd(&nz, 1);
    __syncthreads();
    if (threadIdx.x == 0) g_idx_is64 = (nz == 0) ? 1 : 0;
}

// ---------------- kernel 1: zero aggr + stats ----------------
__global__ void zero_kernel() {
    int idx = blockIdx.x * blockDim.x + threadIdx.x;
    const int n4 = (N_NODES * D) / 4;
    if (idx < n4) {
        ((float4*)g_aggr)[idx] = make_float4(0.f, 0.f, 0.f, 0.f);
    }
    if (blockIdx.x == 0 && threadIdx.x < D) {
        g_sum[threadIdx.x] = 0.f;
        g_sumsq[threadIdx.x] = 0.f;
    }
}

// ---------------- kernel 2: edge scatter-add (warp per edge) ----------------
__device__ __forceinline__ void red_add_v4(float* addr, float4 v) {
    asm volatile("red.global.add.v4.f32 [%0], {%1, %2, %3, %4};"
                 :: "l"(addr), "f"(v.x), "f"(v.y), "f"(v.z), "f"(v.w)
                 : "memory");
}

__global__ void scatter_kernel(const void* __restrict__ edge_index,
                               const float* __restrict__ x) {
    int warp = (blockIdx.x * blockDim.x + threadIdx.x) >> 5;
    if (warp >= N_EDGES) return;
    int lane = threadIdx.x & 31;

    long long src, dst;
    if (g_idx_is64) {
        const long long* e = (const long long*)edge_index;
        src = e[warp];
        dst = e[N_EDGES + warp];
    } else {
        const int* e = (const int*)edge_index;
        src = e[warp];
        dst = e[N_EDGES + warp];
    }
    if ((unsigned long long)src >= N_NODES || (unsigned long long)dst >= N_NODES)
        return;  // safety net; never taken for valid input

    float4 v = ((const float4*)(x + (size_t)src * D))[lane];
    red_add_v4(g_aggr + (size_t)dst * D + lane * 4, v);
}

// ---------------- kernel 3: fused GEMM + bias + BN stats ----------------
// h = x @ W_root + aggr @ W_rel + b_rel   (K = 256 virtual concat)
// Block tile 64(M) x 128(N), 256 threads, each thread 8x4 micro-tile.
#define BM 64
#define KC 32

__global__ __launch_bounds__(256, 2)
void gemm_kernel(const float* __restrict__ x,
                 const float* __restrict__ W_root,
                 const float* __restrict__ W_rel,
                 const float* __restrict__ b_rel) {
    __shared__ float sA[BM][KC];
    __shared__ float sB[KC][D];
    __shared__ float ssum[D];
    __shared__ float ssq[D];

    const int tid = threadIdx.x;
    const int tn = tid & 31;   // column group: cols [tn*4, tn*4+4)
    const int tm = tid >> 5;   // row group: rows [tm*8, tm*8+8)
    const int m0 = blockIdx.x * BM;

    float acc[8][4];
#pragma unroll
    for (int i = 0; i < 8; i++)
#pragma unroll
        for (int j = 0; j < 4; j++) acc[i][j] = 0.f;

#pragma unroll 1
    for (int kc = 0; kc < KTOT / KC; kc++) {
        const int k0 = kc * KC;
        const bool first_half = (k0 < D);
        const float* Asrc = first_half ? x : g_aggr;
        const float* Bsrc = first_half ? W_root : W_rel;
        const int ka = k0 & (D - 1);

        // load A tile: 64 x 32, two float4 per thread
        {
            int r = tid >> 3;            // 0..31
            int c4 = (tid & 7) * 4;      // 0..28
#pragma unroll
            for (int i = 0; i < 2; i++) {
                int row = r + 32 * i;
                int gm = m0 + row;
                float4 v = make_float4(0.f, 0.f, 0.f, 0.f);
                if (gm < N_NODES)
                    v = *(const float4*)(Asrc + (size_t)gm * D + ka + c4);
                *(float4*)&sA[row][c4] = v;
            }
        }
        // load B tile: 32 x 128, four float4 per thread
        {
            int r = tid >> 5;            // 0..7
            int c4 = (tid & 31) * 4;
#pragma unroll
            for (int i = 0; i < 4; i++) {
                int row = r + 8 * i;
                float4 v = *(const float4*)(Bsrc + (size_t)(ka + row) * D + c4);
                *(float4*)&sB[row][c4] = v;
            }
        }
        __syncthreads();

#pragma unroll
        for (int k = 0; k < KC; k++) {
            float4 b = *(float4*)&sB[k][tn * 4];
#pragma unroll
            for (int i = 0; i < 8; i++) {
                float a = sA[tm * 8 + i][k];
                acc[i][0] += a * b.x;
                acc[i][1] += a * b.y;
                acc[i][2] += a * b.z;
                acc[i][3] += a * b.w;
            }
        }
        __syncthreads();
    }

    // epilogue: + b_rel, store h, accumulate column stats
    const int col = tn * 4;
    float4 bb = *(const float4*)(b_rel + col);
    float lsum[4] = {0.f, 0.f, 0.f, 0.f};
    float lsq[4]  = {0.f, 0.f, 0.f, 0.f};

#pragma unroll
    for (int i = 0; i < 8; i++) {
        int gm = m0 + tm * 8 + i;
        if (gm < N_NODES) {
            float4 h;
            h.x = acc[i][0] + bb.x;
            h.y = acc[i][1] + bb.y;
            h.z = acc[i][2] + bb.z;
            h.w = acc[i][3] + bb.w;
            *(float4*)(g_h + (size_t)gm * D + col) = h;
            lsum[0] += h.x; lsum[1] += h.y; lsum[2] += h.z; lsum[3] += h.w;
            lsq[0] += h.x * h.x; lsq[1] += h.y * h.y;
            lsq[2] += h.z * h.z; lsq[3] += h.w * h.w;
        }
    }

    if (tid < D) { ssum[tid] = 0.f; ssq[tid] = 0.f; }
    __syncthreads();
#pragma unroll
    for (int j = 0; j < 4; j++) {
        atomicAdd(&ssum[col + j], lsum[j]);
        atomicAdd(&ssq[col + j], lsq[j]);
    }
    __syncthreads();
    if (tid < D) {
        atomicAdd(&g_sum[tid], ssum[tid]);
        atomicAdd(&g_sumsq[tid], ssq[tid]);
    }
}

// ---------------- kernel 4: finalize BN params ----------------
__global__ void finalize_kernel(const float* __restrict__ gamma,
                                const float* __restrict__ beta) {
    int c = threadIdx.x;
    if (c < D) {
        float inv_n = 1.0f / (float)N_NODES;
        float mean = g_sum[c] * inv_n;
        float var = g_sumsq[c] * inv_n - mean * mean;
        float sc = gamma[c] * rsqrtf(var + EPS);
        g_scale[c] = sc;
        g_shift[c] = beta[c] - mean * sc;
    }
}

// ---------------- kernel 5: normalize + ReLU ----------------
__global__ void norm_kernel(float* __restrict__ out) {
    int idx = blockIdx.x * blockDim.x + threadIdx.x;
    const int n4 = (N_NODES * D) / 4;
    if (idx >= n4) return;
    int c4 = (idx & (D / 4 - 1)) * 4;   // column of first element
    float4 h = ((const float4*)g_h)[idx];
    float4 sc = *(const float4*)(g_scale + c4);
    float4 sh = *(const float4*)(g_shift + c4);
    float4 o;
    o.x = fmaxf(h.x * sc.x + sh.x, 0.f);
    o.y = fmaxf(h.y * sc.y + sh.y, 0.f);
    o.z = fmaxf(h.z * sc.z + sh.z, 0.f);
    o.w = fmaxf(h.w * sc.w + sh.w, 0.f);
    ((float4*)out)[idx] = o;
}

// ---------------- launch ----------------
extern "C" void kernel_launch(void* const* d_in, const int* in_sizes, int n_in,
                              void* d_out, int out_size) {
    const float* x      = (const float*)d_in[0];
    const void*  eidx   = d_in[1];                 // int32 (probable) or int64
    const float* W_root = (const float*)d_in[2];
    const float* W_rel  = (const float*)d_in[3];
    const float* b_rel  = (const float*)d_in[4];
    const float* gamma  = (const float*)d_in[5];
    const float* beta   = (const float*)d_in[6];
    float*       out    = (float*)d_out;

    probe_kernel<<<1, 64>>>((const int*)eidx);

    const int n4 = (N_NODES * D) / 4;          // 3.2M float4
    zero_kernel<<<(n4 + 255) / 256, 256>>>();

    // warp per edge, 8 edges per 256-thread block
    scatter_kernel<<<(N_EDGES + 7) / 8, 256>>>(eidx, x);

    gemm_kernel<<<(N_NODES + BM - 1) / BM, 256>>>(x, W_root, W_rel, b_rel);

    finalize_kernel<<<1, 128>>>(gamma, beta);

    norm_kernel<<<(n4 + 255) / 256, 256>>>(out);
}